// round 2
// baseline (speedup 1.0000x reference)
#include <cuda_runtime.h>

#define Bsz 128
#define Hdim 256
#define Wdim 1024
#define N_HOLES 5
#define PROB 1.0f
#define HOLE_MINW (Wdim / 10)              // 102
#define HOLE_MINH (Hdim / 10)              // 25
#define N_TOTAL ((long long)Bsz * Hdim * Wdim)   // 33,554,432

#define CHUNKS 16                          // row-chunks per image
#define ROWS_PER_CHUNK (Hdim / CHUNKS)     // 16
#define NBLOCKS (Bsz * CHUNKS)             // 2048
#define QUADS_PER_ROW (Wdim / 4)           // 256 == blockDim.x

__device__ float g_partials[NBLOCKS];
__device__ float g_mean;
__device__ int   g_count = 0;              // last block resets -> replay-safe

// One image-row-chunk per block. Copies x->out (skipping quads fully inside an
// active hole -- the fill kernel overwrites those), accumulates the global sum.
// The last block to finish reduces all partials into g_mean.
__global__ void __launch_bounds__(256) copy_reduce_kernel(
    const float* __restrict__ x, float* __restrict__ out,
    const int* __restrict__ xs, const int* __restrict__ ys,
    const int* __restrict__ xs_w_raw, const int* __restrict__ ys_h_raw,
    const float* __restrict__ act_rand)
{
    const int b = blockIdx.x;
    __shared__ int hx0[N_HOLES], hx1[N_HOLES], hy0[N_HOLES], hy1[N_HOLES];
    __shared__ int hact[N_HOLES];
    if (threadIdx.x < N_HOLES) {
        int i = b * N_HOLES + threadIdx.x;
        int hw = xs_w_raw[i] + HOLE_MINW;
        int hh = ys_h_raw[i] + HOLE_MINH;
        int cx = xs[i], cy = ys[i];
        hx0[threadIdx.x] = min(max(cx - hw / 2, 0), Wdim - 2);
        hx1[threadIdx.x] = min(max(cx + hw / 2, 1), Wdim - 1);
        hy0[threadIdx.x] = min(max(cy - hh / 2, 0), Hdim - 2);
        hy1[threadIdx.x] = min(max(cy + hh / 2, 1), Hdim - 1);
        hact[threadIdx.x] = (act_rand[i] < PROB) ? 1 : 0;
    }
    __syncthreads();

    const int h0 = blockIdx.y * ROWS_PER_CHUNK;
    const float4* __restrict__ xi =
        (const float4*)(x + (size_t)b * Hdim * Wdim);
    float4* __restrict__ oi = (float4*)(out + (size_t)b * Hdim * Wdim);

    const int q  = threadIdx.x;            // quad index within row
    const int w0 = q * 4;

    float s = 0.0f;
    #pragma unroll 4
    for (int r = 0; r < ROWS_PER_CHUNK; ++r) {
        const int h = h0 + r;
        const size_t idx = (size_t)h * QUADS_PER_ROW + q;
        float4 v = __ldcs(&xi[idx]);
        s += (v.x + v.y) + (v.z + v.w);
        bool skip = false;
        #pragma unroll
        for (int n = 0; n < N_HOLES; ++n)
            skip |= hact[n] && (h >= hy0[n]) && (h <= hy1[n]) &&
                    (w0 >= hx0[n]) && (w0 + 3 <= hx1[n]);
        if (!skip) __stcs(&oi[idx], v);
    }

    // block reduce (float)
    #pragma unroll
    for (int o = 16; o > 0; o >>= 1)
        s += __shfl_down_sync(0xFFFFFFFFu, s, o);
    __shared__ float ws[8];
    const int lane = threadIdx.x & 31, warp = threadIdx.x >> 5;
    if (lane == 0) ws[warp] = s;
    __syncthreads();
    __shared__ int is_last;
    if (threadIdx.x == 0) {
        float v = ws[0];
        #pragma unroll
        for (int i = 1; i < 8; ++i) v += ws[i];
        int bid = blockIdx.y * gridDim.x + blockIdx.x;
        g_partials[bid] = v;
        __threadfence();
        int ticket = atomicAdd(&g_count, 1);
        is_last = (ticket == NBLOCKS - 1);
    }
    __syncthreads();

    if (is_last) {
        // this block reduces all 2048 partials in fixed order (deterministic)
        double s2 = 0.0;
        for (int i = threadIdx.x; i < NBLOCKS; i += 256)
            s2 += (double)g_partials[i];
        #pragma unroll
        for (int o = 16; o > 0; o >>= 1)
            s2 += __shfl_down_sync(0xFFFFFFFFu, s2, o);
        __shared__ double wd[8];
        if (lane == 0) wd[warp] = s2;
        __syncthreads();
        if (threadIdx.x == 0) {
            double t = wd[0];
            #pragma unroll
            for (int i = 1; i < 8; ++i) t += wd[i];
            g_mean = (float)(t / (double)N_TOTAL);
            g_count = 0;                   // reset for next graph replay
        }
    }
}

// One hole per blockIdx.x; rows strided over blockIdx.y.
__global__ void __launch_bounds__(256) fill_holes_kernel(
    const int* __restrict__ xs, const int* __restrict__ ys,
    const int* __restrict__ xs_w_raw, const int* __restrict__ ys_h_raw,
    const float* __restrict__ act_rand, float* __restrict__ out)
{
    const int hole = blockIdx.x;
    const int b = hole / N_HOLES;
    if (!(act_rand[hole] < PROB)) return;

    const int cw = xs[hole], ch = ys[hole];
    const int hw = xs_w_raw[hole] + HOLE_MINW;
    const int hh = ys_h_raw[hole] + HOLE_MINH;
    const int x0 = min(max(cw - hw / 2, 0), Wdim - 2);
    const int x1 = min(max(cw + hw / 2, 1), Wdim - 1);
    const int y0 = min(max(ch - hh / 2, 0), Hdim - 2);
    const int y1 = min(max(ch + hh / 2, 1), Hdim - 1);

    const float fill = g_mean;
    float* base = out + (size_t)b * Hdim * Wdim;
    for (int h = y0 + blockIdx.y; h <= y1; h += gridDim.y) {
        float* row = base + (size_t)h * Wdim;
        for (int w = x0 + threadIdx.x; w <= x1; w += blockDim.x)
            __stcs(&row[w], fill);
    }
}

extern "C" void kernel_launch(void* const* d_in, const int* in_sizes, int n_in,
                              void* d_out, int out_size) {
    const float* x        = (const float*)d_in[0];
    const int*   xs       = (const int*)d_in[1];
    const int*   ys       = (const int*)d_in[2];
    const int*   xs_w_raw = (const int*)d_in[3];
    const int*   ys_h_raw = (const int*)d_in[4];
    const float* act_rand = (const float*)d_in[5];
    float* out = (float*)d_out;

    dim3 cgrid(Bsz, CHUNKS);
    copy_reduce_kernel<<<cgrid, 256>>>(x, out, xs, ys, xs_w_raw, ys_h_raw,
                                       act_rand);

    dim3 fgrid(Bsz * N_HOLES, 16);
    fill_holes_kernel<<<fgrid, 256>>>(xs, ys, xs_w_raw, ys_h_raw, act_rand, out);
}

// round 3
// speedup vs baseline: 1.4495x; 1.4495x over previous
#include <cuda_runtime.h>

#define Bsz 128
#define Hdim 256
#define Wdim 1024
#define N_HOLES 5
#define PROB 1.0f
#define HOLE_MINW (Wdim / 10)              // 102
#define HOLE_MINH (Hdim / 10)              // 25
#define N_TOTAL ((long long)Bsz * Hdim * Wdim)   // 33,554,432

#define CR_BLOCKS 1184                     // 148 SMs * 8
#define CR_THREADS 256

__device__ float g_partials[CR_BLOCKS];
__device__ float g_mean;
__device__ int   g_count = 0;              // last block resets -> replay-safe

// Grid-stride full copy x->out + global sum. Last block to finish reduces the
// per-block partials into g_mean (fixed order -> deterministic), then resets
// the ticket counter so the kernel is graph-replay-safe.
__global__ void __launch_bounds__(CR_THREADS) copy_reduce_kernel(
    const float4* __restrict__ x, float4* __restrict__ out, long long n4)
{
    long long i = (long long)blockIdx.x * blockDim.x + threadIdx.x;
    const long long stride = (long long)gridDim.x * blockDim.x;
    float s = 0.0f;
    #pragma unroll 4
    for (; i < n4; i += stride) {
        float4 v = x[i];
        out[i] = v;
        s += (v.x + v.y) + (v.z + v.w);
    }

    // block reduce
    #pragma unroll
    for (int o = 16; o > 0; o >>= 1)
        s += __shfl_down_sync(0xFFFFFFFFu, s, o);
    __shared__ float ws[8];
    const int lane = threadIdx.x & 31, warp = threadIdx.x >> 5;
    if (lane == 0) ws[warp] = s;
    __syncthreads();
    __shared__ int is_last;
    if (threadIdx.x == 0) {
        float v = ws[0];
        #pragma unroll
        for (int k = 1; k < 8; ++k) v += ws[k];
        g_partials[blockIdx.x] = v;
        __threadfence();
        int ticket = atomicAdd(&g_count, 1);
        is_last = (ticket == CR_BLOCKS - 1);
    }
    __syncthreads();

    if (is_last) {
        double s2 = 0.0;
        for (int k = threadIdx.x; k < CR_BLOCKS; k += CR_THREADS)
            s2 += (double)g_partials[k];
        #pragma unroll
        for (int o = 16; o > 0; o >>= 1)
            s2 += __shfl_down_sync(0xFFFFFFFFu, s2, o);
        __shared__ double wd[8];
        if (lane == 0) wd[warp] = s2;
        __syncthreads();
        if (threadIdx.x == 0) {
            double t = wd[0];
            #pragma unroll
            for (int k = 1; k < 8; ++k) t += wd[k];
            g_mean = (float)(t / (double)N_TOTAL);
            g_count = 0;                   // reset for next replay
        }
    }
}

// One hole per blockIdx.x; rows strided over blockIdx.y. Vectorized interior
// (float4) with <=3-element scalar edges per row.
__global__ void __launch_bounds__(256) fill_holes_kernel(
    const int* __restrict__ xs, const int* __restrict__ ys,
    const int* __restrict__ xs_w_raw, const int* __restrict__ ys_h_raw,
    const float* __restrict__ act_rand, float* __restrict__ out)
{
    const int hole = blockIdx.x;
    const int b = hole / N_HOLES;
    if (!(act_rand[hole] < PROB)) return;

    const int cw = xs[hole], ch = ys[hole];
    const int hw = xs_w_raw[hole] + HOLE_MINW;
    const int hh = ys_h_raw[hole] + HOLE_MINH;
    const int x0 = min(max(cw - hw / 2, 0), Wdim - 2);
    const int x1 = min(max(cw + hw / 2, 1), Wdim - 1);
    const int y0 = min(max(ch - hh / 2, 0), Hdim - 2);
    const int y1 = min(max(ch + hh / 2, 1), Hdim - 1);

    const int a0 = (x0 + 3) & ~3;          // first aligned float index
    const int a1 = (x1 + 1) & ~3;          // exclusive aligned end
    const int nvec = (a1 - a0) >> 2;       // float4 count (<= 103 < blockDim)

    const float fill = g_mean;
    const float4 f4 = make_float4(fill, fill, fill, fill);
    const int t = threadIdx.x;

    float* const base = out + (size_t)b * Hdim * Wdim;
    for (int h = y0 + blockIdx.y; h <= y1; h += gridDim.y) {
        float* const row = base + (size_t)h * Wdim;
        if (t < 4) {                       // scalar edges
            int wl = x0 + t;
            if (wl < a0) row[wl] = fill;
            int wr = a1 + t;
            if (wr <= x1) row[wr] = fill;
        }
        if (t < nvec)
            reinterpret_cast<float4*>(row + a0)[t] = f4;
    }
}

extern "C" void kernel_launch(void* const* d_in, const int* in_sizes, int n_in,
                              void* d_out, int out_size) {
    const float* x        = (const float*)d_in[0];
    const int*   xs       = (const int*)d_in[1];
    const int*   ys       = (const int*)d_in[2];
    const int*   xs_w_raw = (const int*)d_in[3];
    const int*   ys_h_raw = (const int*)d_in[4];
    const float* act_rand = (const float*)d_in[5];
    float* out = (float*)d_out;

    copy_reduce_kernel<<<CR_BLOCKS, CR_THREADS>>>(
        (const float4*)x, (float4*)out, N_TOTAL / 4);

    dim3 fgrid(Bsz * N_HOLES, 8);
    fill_holes_kernel<<<fgrid, 256>>>(xs, ys, xs_w_raw, ys_h_raw, act_rand, out);
}

// round 4
// speedup vs baseline: 1.5008x; 1.0354x over previous
#include <cuda_runtime.h>

#define Bsz 128
#define Hdim 256
#define Wdim 1024
#define N_HOLES 5
#define PROB 1.0f
#define HOLE_MINW (Wdim / 10)              // 102
#define HOLE_MINH (Hdim / 10)              // 25
#define N_TOTAL ((long long)Bsz * Hdim * Wdim)   // 33,554,432

#define CR_BLOCKS 1184                     // 148 SMs * 8
#define CR_THREADS 256

__device__ float g_partials[CR_BLOCKS];
__device__ float g_mean;
__device__ int   g_count = 0;              // last block resets -> replay-safe

// Grid-stride full copy x->out + global sum. Last block to finish reduces the
// per-block partials into g_mean (fixed order -> deterministic), then resets
// the ticket counter so the kernel is graph-replay-safe.
__global__ void __launch_bounds__(CR_THREADS) copy_reduce_kernel(
    const float4* __restrict__ x, float4* __restrict__ out, long long n4)
{
    long long i = (long long)blockIdx.x * blockDim.x + threadIdx.x;
    const long long stride = (long long)gridDim.x * blockDim.x;
    float s = 0.0f;
    #pragma unroll 4
    for (; i < n4; i += stride) {
        float4 v = x[i];
        out[i] = v;
        s += (v.x + v.y) + (v.z + v.w);
    }

    // block reduce
    #pragma unroll
    for (int o = 16; o > 0; o >>= 1)
        s += __shfl_down_sync(0xFFFFFFFFu, s, o);
    __shared__ float ws[8];
    const int lane = threadIdx.x & 31, warp = threadIdx.x >> 5;
    if (lane == 0) ws[warp] = s;
    __syncthreads();
    __shared__ int is_last;
    if (threadIdx.x == 0) {
        float v = ws[0];
        #pragma unroll
        for (int k = 1; k < 8; ++k) v += ws[k];
        g_partials[blockIdx.x] = v;
        __threadfence();
        int ticket = atomicAdd(&g_count, 1);
        is_last = (ticket == CR_BLOCKS - 1);
    }
    __syncthreads();

    if (is_last) {
        double s2 = 0.0;
        for (int k = threadIdx.x; k < CR_BLOCKS; k += CR_THREADS)
            s2 += (double)g_partials[k];
        #pragma unroll
        for (int o = 16; o > 0; o >>= 1)
            s2 += __shfl_down_sync(0xFFFFFFFFu, s2, o);
        __shared__ double wd[8];
        if (lane == 0) wd[warp] = s2;
        __syncthreads();
        if (threadIdx.x == 0) {
            double t = wd[0];
            #pragma unroll
            for (int k = 1; k < 8; ++k) t += wd[k];
            g_mean = (float)(t / (double)N_TOTAL);
            g_count = 0;                   // reset for next replay
        }
    }
}

// ONE block per hole (640 blocks = single wave). 256 threads split as
// (qx = t & 63: quad lane, ry = t >> 6: row lane). Each block sweeps its
// whole rect: float4 interior + <=3-element scalar edges per row.
__global__ void __launch_bounds__(256) fill_holes_kernel(
    const int* __restrict__ xs, const int* __restrict__ ys,
    const int* __restrict__ xs_w_raw, const int* __restrict__ ys_h_raw,
    const float* __restrict__ act_rand, float* __restrict__ out)
{
    const int hole = blockIdx.x;
    const int b = hole / N_HOLES;
    if (!(act_rand[hole] < PROB)) return;

    const int cw = xs[hole], ch = ys[hole];
    const int hw = xs_w_raw[hole] + HOLE_MINW;
    const int hh = ys_h_raw[hole] + HOLE_MINH;
    const int x0 = min(max(cw - hw / 2, 0), Wdim - 2);
    const int x1 = min(max(cw + hw / 2, 1), Wdim - 1);
    const int y0 = min(max(ch - hh / 2, 0), Hdim - 2);
    const int y1 = min(max(ch + hh / 2, 1), Hdim - 1);

    const int a0 = (x0 + 3) & ~3;          // first aligned float index
    const int a1 = (x1 + 1) & ~3;          // exclusive aligned end
    const int nvec = (a1 - a0) >> 2;       // float4 interior count

    const float fill = g_mean;
    const float4 f4 = make_float4(fill, fill, fill, fill);

    const int qx = threadIdx.x & 63;       // quad lane
    const int ry = threadIdx.x >> 6;       // row lane (0..3)

    // edge assignments (predicated, constant per thread)
    const int wl = x0 + qx;                // left-edge scalar (qx < 3 region)
    const bool do_l = (qx < 3) && (wl < a0);
    const int wr = a1 + (qx - 3);          // right-edge scalar (qx in [3,6))
    const bool do_r = (qx >= 3) && (qx < 6) && (wr <= x1);

    float* const base = out + (size_t)b * Hdim * Wdim + a0;
    for (int h = y0 + ry; h <= y1; h += 4) {
        float* const row = base + (size_t)h * Wdim;   // points at a0
        if (do_l) row[wl - a0] = fill;
        if (do_r) row[wr - a0] = fill;
        float4* const rowv = reinterpret_cast<float4*>(row);
        for (int q = qx; q < nvec; q += 64)
            rowv[q] = f4;
    }
}

extern "C" void kernel_launch(void* const* d_in, const int* in_sizes, int n_in,
                              void* d_out, int out_size) {
    const float* x        = (const float*)d_in[0];
    const int*   xs       = (const int*)d_in[1];
    const int*   ys       = (const int*)d_in[2];
    const int*   xs_w_raw = (const int*)d_in[3];
    const int*   ys_h_raw = (const int*)d_in[4];
    const float* act_rand = (const float*)d_in[5];
    float* out = (float*)d_out;

    copy_reduce_kernel<<<CR_BLOCKS, CR_THREADS>>>(
        (const float4*)x, (float4*)out, N_TOTAL / 4);

    fill_holes_kernel<<<Bsz * N_HOLES, 256>>>(xs, ys, xs_w_raw, ys_h_raw,
                                              act_rand, out);
}